// round 1
// baseline (speedup 1.0000x reference)
#include <cuda_runtime.h>
#include <math_constants.h>
#include <cstdint>

// Problem constants
#define NPTS 65536
#define KK   64
#define CH   32          // chunks over N for kernel A
#define LPB  (NPTS/CH)   // 2048 points per block in kernel A
#define BB   8
#define LOG2E 1.4426950408889634f
#define PI_CONST ((1.0f + 1e-8f) / 65536.0f)     // pi_k, data independent
#define INV_DENOM (1.0f / (1.0f + 2e-8f))        // 1/(Npi + eps)

// Scratch (device globals: no allocation allowed)
__device__ float g_part[16][CH][KK][5];   // [bt][chunk][k][{m, Z, Sx, Sy, Sz}]
__device__ float g_mu[16][KK][3];         // bt = t*8 + b ; t=0 template, t=1 source
__device__ float g_RT[BB][12];            // 9 R (row major) + 3 T

__device__ __forceinline__ float ex2f(float x) {
    float r; asm("ex2.approx.f32 %0, %1;" : "=f"(r) : "f"(x)); return r;
}
__device__ __forceinline__ float lg2f(float x) {
    float r; asm("lg2.approx.f32 %0, %1;" : "=f"(r) : "f"(x)); return r;
}

// ---------------------------------------------------------------------------
// Kernel A: per (b, tensor, chunk) online softmax-weighted sums for all K=64.
// Block = 256 threads = 64 k-lanes x 4 point-slots. Points staged in smem.
// Logits pre-scaled to log2 domain (W folded with log2(e)) so exp == 1 MUFU.
// ---------------------------------------------------------------------------
__global__ void __launch_bounds__(256) kA(const float* __restrict__ tmpl,
                                          const float* __restrict__ src,
                                          const float* __restrict__ W)
{
    __shared__ float xs[LPB], ys[LPB], zs[LPB];
    const int bt = blockIdx.y;
    const int b  = bt & 7;
    const int t  = bt >> 3;
    const float* f = (t ? src : tmpl) + (size_t)b * 3 * NPTS;
    const int base = blockIdx.x * LPB;
    const int tid  = threadIdx.x;

    const float4* gx = (const float4*)(f + base);
    const float4* gy = (const float4*)(f + NPTS   + base);
    const float4* gz = (const float4*)(f + 2*NPTS + base);
    float4* sx4 = (float4*)xs; float4* sy4 = (float4*)ys; float4* sz4 = (float4*)zs;
    #pragma unroll
    for (int i = tid; i < LPB/4; i += 256) { sx4[i] = gx[i]; sy4[i] = gy[i]; sz4[i] = gz[i]; }
    __syncthreads();

    const int k    = tid & 63;
    const int slot = tid >> 6;
    const float wx = W[k]        * LOG2E;
    const float wy = W[64 + k]   * LOG2E;
    const float wz = W[128 + k]  * LOG2E;

    float m = -CUDART_INF_F, s = 0.f, ax = 0.f, ay = 0.f, az = 0.f;

    const float4* X = (const float4*)xs + slot * (LPB/4/4);  // 128 float4 per slot
    const float4* Y = (const float4*)ys + slot * (LPB/4/4);
    const float4* Z = (const float4*)zs + slot * (LPB/4/4);

    #pragma unroll 4
    for (int i = 0; i < LPB/4/4; i++) {
        float4 px = X[i], py = Y[i], pz = Z[i];
        float l0 = fmaf(wx, px.x, fmaf(wy, py.x, wz * pz.x));
        float l1 = fmaf(wx, px.y, fmaf(wy, py.y, wz * pz.y));
        float l2 = fmaf(wx, px.z, fmaf(wy, py.z, wz * pz.z));
        float l3 = fmaf(wx, px.w, fmaf(wy, py.w, wz * pz.w));
        float gm = fmaxf(fmaxf(l0, l1), fmaxf(l2, l3));
        if (gm > m) {                      // rare after warmup
            float c = ex2f(m - gm);
            s *= c; ax *= c; ay *= c; az *= c; m = gm;
        }
        float e0 = ex2f(l0 - m), e1 = ex2f(l1 - m), e2 = ex2f(l2 - m), e3 = ex2f(l3 - m);
        s += (e0 + e1) + (e2 + e3);
        ax = fmaf(e0, px.x, ax); ax = fmaf(e1, px.y, ax); ax = fmaf(e2, px.z, ax); ax = fmaf(e3, px.w, ax);
        ay = fmaf(e0, py.x, ay); ay = fmaf(e1, py.y, ay); ay = fmaf(e2, py.z, ay); ay = fmaf(e3, py.w, ay);
        az = fmaf(e0, pz.x, az); az = fmaf(e1, pz.y, az); az = fmaf(e2, pz.z, az); az = fmaf(e3, pz.w, az);
    }
    __syncthreads();

    // combine 4 slots per k (reuse smem)
    xs[tid] = m; ys[tid] = s; zs[tid] = ax; xs[256 + tid] = ay; ys[256 + tid] = az;
    __syncthreads();
    if (slot == 0) {
        float M = m, S = s, AX = ax, AY = ay, AZ = az;
        #pragma unroll
        for (int o = 1; o < 4; o++) {
            int j = o * 64 + k;
            float mo = xs[j], so = ys[j], axo = zs[j], ayo = xs[256 + j], azo = ys[256 + j];
            float nm = fmaxf(M, mo);
            float ca = ex2f(M - nm), cb = ex2f(mo - nm);
            S = S * ca + so * cb;
            AX = AX * ca + axo * cb;
            AY = AY * ca + ayo * cb;
            AZ = AZ * ca + azo * cb;
            M = nm;
        }
        float* p = g_part[bt][blockIdx.x][k];
        p[0] = M; p[1] = S; p[2] = AX; p[3] = AY; p[4] = AZ;
    }
}

// ---------------------------------------------------------------------------
// Kernel B: reduce the 32 chunks per (bt,k) -> mu
// ---------------------------------------------------------------------------
__global__ void __launch_bounds__(256) kB()
{
    int item = blockIdx.x * 256 + threadIdx.x;  // 0..1023
    if (item >= 16 * KK) return;
    int bt = item >> 6, k = item & 63;
    float M = -CUDART_INF_F, S = 0.f, AX = 0.f, AY = 0.f, AZ = 0.f;
    #pragma unroll 4
    for (int c = 0; c < CH; c++) {
        const float* p = g_part[bt][c][k];
        float mo = p[0], so = p[1], axo = p[2], ayo = p[3], azo = p[4];
        float nm = fmaxf(M, mo);
        float ca = ex2f(M - nm), cb = ex2f(mo - nm);
        S = S * ca + so * cb;
        AX = AX * ca + axo * cb;
        AY = AY * ca + ayo * cb;
        AZ = AZ * ca + azo * cb;
        M = nm;
    }
    float inv = INV_DENOM / S;
    g_mu[bt][k][0] = AX * inv;
    g_mu[bt][k][1] = AY * inv;
    g_mu[bt][k][2] = AZ * inv;
}

// ---------------------------------------------------------------------------
// Kernel C: per batch, 3x3 cross-covariance of means + polar decomposition
// (scaled Newton, float), sign fix identical to reference, T. One warp/batch.
// ---------------------------------------------------------------------------
__device__ void polar3(const float* Win, float* Q)
{
    float X[9];
    #pragma unroll
    for (int i = 0; i < 9; i++) X[i] = Win[i];
    #pragma unroll 1
    for (int it = 0; it < 18; it++) {
        float c00 = X[4]*X[8] - X[5]*X[7];
        float c01 = X[5]*X[6] - X[3]*X[8];
        float c02 = X[3]*X[7] - X[4]*X[6];
        float c10 = X[2]*X[7] - X[1]*X[8];
        float c11 = X[0]*X[8] - X[2]*X[6];
        float c12 = X[1]*X[6] - X[0]*X[7];
        float c20 = X[1]*X[5] - X[2]*X[4];
        float c21 = X[2]*X[3] - X[0]*X[5];
        float c22 = X[0]*X[4] - X[1]*X[3];
        float det = X[0]*c00 + X[1]*c01 + X[2]*c02;
        float g  = ex2f(-0.3333333333f * lg2f(fabsf(det)));  // |det|^(-1/3)
        float h  = 0.5f * g;
        float h2 = __fdividef(0.5f, g * det);                // 0.5 * (1/g) / det
        X[0] = h*X[0] + h2*c00; X[1] = h*X[1] + h2*c01; X[2] = h*X[2] + h2*c02;
        X[3] = h*X[3] + h2*c10; X[4] = h*X[4] + h2*c11; X[5] = h*X[5] + h2*c12;
        X[6] = h*X[6] + h2*c20; X[7] = h*X[7] + h2*c21; X[8] = h*X[8] + h2*c22;
    }
    #pragma unroll
    for (int i = 0; i < 9; i++) Q[i] = X[i];
}

__global__ void __launch_bounds__(32) kC()
{
    const int b = blockIdx.x;
    const int lane = threadIdx.x;
    float ms0[3], ms1[3], mt0[3], mt1[3];
    #pragma unroll
    for (int d = 0; d < 3; d++) {
        ms0[d] = g_mu[8 + b][lane][d];
        ms1[d] = g_mu[8 + b][lane + 32][d];
        mt0[d] = g_mu[b][lane][d];
        mt1[d] = g_mu[b][lane + 32][d];
    }
    float ss[3], st[3];
    #pragma unroll
    for (int d = 0; d < 3; d++) { ss[d] = ms0[d] + ms1[d]; st[d] = mt0[d] + mt1[d]; }
    #pragma unroll
    for (int off = 16; off; off >>= 1) {
        #pragma unroll
        for (int d = 0; d < 3; d++) {
            ss[d] += __shfl_xor_sync(0xffffffffu, ss[d], off);
            st[d] += __shfl_xor_sync(0xffffffffu, st[d], off);
        }
    }
    float cx[3], cy[3];
    #pragma unroll
    for (int d = 0; d < 3; d++) { cx[d] = PI_CONST * ss[d]; cy[d] = PI_CONST * st[d]; }

    float Wm[9];
    #pragma unroll
    for (int d = 0; d < 3; d++)
        #pragma unroll
        for (int e = 0; e < 3; e++)
            Wm[d*3+e] = (mt0[d] - cy[d]) * (ms0[e] - cx[e])
                      + (mt1[d] - cy[d]) * (ms1[e] - cx[e]);
    #pragma unroll
    for (int off = 16; off; off >>= 1)
        #pragma unroll
        for (int i = 0; i < 9; i++)
            Wm[i] += __shfl_xor_sync(0xffffffffu, Wm[i], off);

    if (lane == 0) {
        #pragma unroll
        for (int i = 0; i < 9; i++) Wm[i] *= PI_CONST;
        float Q[9];
        polar3(Wm, Q);
        // det sign -> flip LAST COLUMN (matches reference Vh[:,:, -1] *= sign(det))
        float det = Q[0]*(Q[4]*Q[8]-Q[5]*Q[7])
                  - Q[1]*(Q[3]*Q[8]-Q[5]*Q[6])
                  + Q[2]*(Q[3]*Q[7]-Q[4]*Q[6]);
        if (det < 0.f) { Q[2] = -Q[2]; Q[5] = -Q[5]; Q[8] = -Q[8]; }
        float T0 = cy[0] - (Q[0]*cx[0] + Q[1]*cx[1] + Q[2]*cx[2]);
        float T1 = cy[1] - (Q[3]*cx[0] + Q[4]*cx[1] + Q[5]*cx[2]);
        float T2 = cy[2] - (Q[6]*cx[0] + Q[7]*cx[1] + Q[8]*cx[2]);
        float* rt = g_RT[b];
        #pragma unroll
        for (int i = 0; i < 9; i++) rt[i] = Q[i];
        rt[9] = T0; rt[10] = T1; rt[11] = T2;
    }
}

// ---------------------------------------------------------------------------
// Kernel D: aligned[b,n,:] = R * src_pts[b,n,:] + T, smem-staged coalesced I/O
// ---------------------------------------------------------------------------
__global__ void __launch_bounds__(256) kD(const float* __restrict__ src,
                                          float* __restrict__ out)
{
    __shared__ float so[3072];
    __shared__ float rt[12];
    const int b = blockIdx.x >> 6;
    const int tile = blockIdx.x & 63;
    const int tid = threadIdx.x;
    if (tid < 12) rt[tid] = g_RT[b][tid];
    __syncthreads();

    const int base = tile * 1024;
    const float* f = src + (size_t)b * 3 * NPTS;
    float4 px = *(const float4*)(f + base + tid * 4);
    float4 py = *(const float4*)(f + NPTS + base + tid * 4);
    float4 pz = *(const float4*)(f + 2*NPTS + base + tid * 4);

    float r0 = rt[0], r1 = rt[1], r2 = rt[2];
    float r3 = rt[3], r4 = rt[4], r5 = rt[5];
    float r6 = rt[6], r7 = rt[7], r8 = rt[8];
    float t0 = rt[9], t1 = rt[10], t2 = rt[11];

    float X[4] = {px.x, px.y, px.z, px.w};
    float Y[4] = {py.x, py.y, py.z, py.w};
    float Z[4] = {pz.x, pz.y, pz.z, pz.w};
    #pragma unroll
    for (int j = 0; j < 4; j++) {
        float ox = fmaf(r0, X[j], fmaf(r1, Y[j], fmaf(r2, Z[j], t0)));
        float oy = fmaf(r3, X[j], fmaf(r4, Y[j], fmaf(r5, Z[j], t1)));
        float oz = fmaf(r6, X[j], fmaf(r7, Y[j], fmaf(r8, Z[j], t2)));
        int p = (tid * 4 + j) * 3;
        so[p] = ox; so[p + 1] = oy; so[p + 2] = oz;
    }
    __syncthreads();

    float4* ob = (float4*)(out + ((size_t)b * NPTS + base) * 3);
    const float4* sb = (const float4*)so;
    #pragma unroll
    for (int i = tid; i < 768; i += 256) ob[i] = sb[i];
}

// ---------------------------------------------------------------------------
extern "C" void kernel_launch(void* const* d_in, const int* in_sizes, int n_in,
                              void* d_out, int out_size)
{
    const float* tmpl = (const float*)d_in[0];   // (8,3,65536)
    const float* src  = (const float*)d_in[1];   // (8,3,65536)
    const float* W    = (const float*)d_in[2];   // (3,64)
    float* out        = (float*)d_out;           // (8,65536,3)

    kA<<<dim3(CH, 16), 256>>>(tmpl, src, W);
    kB<<<4, 256>>>();
    kC<<<BB, 32>>>();
    kD<<<BB * (NPTS / 1024), 256>>>(src, out);
}

// round 2
// speedup vs baseline: 1.2888x; 1.2888x over previous
#include <cuda_runtime.h>
#include <math_constants.h>
#include <cstdint>

typedef unsigned long long ull;

#define NPTS 65536
#define KK   64
#define CH   32          // chunks over N for kernel A
#define LPB  (NPTS/CH)   // 2048 points per block in kernel A
#define BB   8
#define LOG2E 1.4426950408889634f
#define PI_CONST ((1.0f + 1e-8f) / 65536.0f)
#define INV_DENOM (1.0f / (1.0f + 2e-8f))

// Scratch (device globals: no allocation allowed)
__device__ float g_part[16][CH][KK][4];   // [bt][chunk][k][{S, Sx, Sy, Sz}]
__device__ float g_RT[BB][12];            // 9 R (row major) + 3 T

__device__ __forceinline__ float ex2f(float x) {
    float r; asm("ex2.approx.f32 %0, %1;" : "=f"(r) : "f"(x)); return r;
}
__device__ __forceinline__ float lg2f(float x) {
    float r; asm("lg2.approx.f32 %0, %1;" : "=f"(r) : "f"(x)); return r;
}

// ---- packed f32x2 helpers (Blackwell) ----
__device__ __forceinline__ ull fma2(ull a, ull b, ull c) {
    ull d; asm("fma.rn.f32x2 %0, %1, %2, %3;" : "=l"(d) : "l"(a), "l"(b), "l"(c)); return d;
}
__device__ __forceinline__ ull mul2(ull a, ull b) {
    ull d; asm("mul.rn.f32x2 %0, %1, %2;" : "=l"(d) : "l"(a), "l"(b)); return d;
}
__device__ __forceinline__ ull add2(ull a, ull b) {
    ull d; asm("add.rn.f32x2 %0, %1, %2;" : "=l"(d) : "l"(a), "l"(b)); return d;
}
__device__ __forceinline__ ull pack2(float lo, float hi) {
    ull r; asm("mov.b64 %0, {%1, %2};" : "=l"(r) : "f"(lo), "f"(hi)); return r;
}
__device__ __forceinline__ void unpack2(ull v, float& lo, float& hi) {
    asm("mov.b64 {%0, %1}, %2;" : "=f"(lo), "=f"(hi) : "l"(v));
}

union F4u { float4 f; ull u[2]; };

// ---------------------------------------------------------------------------
// Kernel A: per (b, tensor, chunk): plain-sum softmax numerators for all K=64.
// No max-tracking (logits bounded, fp32 range is ample). Packed f32x2 math.
// Block = 256 threads = 64 k-lanes x 4 point-slots. Points staged in smem;
// all lanes of a warp read the same smem address (broadcast, conflict-free).
// ---------------------------------------------------------------------------
__global__ void __launch_bounds__(256) kA(const float* __restrict__ tmpl,
                                          const float* __restrict__ src,
                                          const float* __restrict__ W)
{
    __shared__ float xs[LPB], ys[LPB], zs[LPB];
    const int bt = blockIdx.y;
    const int b  = bt & 7;
    const int t  = bt >> 3;
    const float* f = (t ? src : tmpl) + (size_t)b * 3 * NPTS;
    const int base = blockIdx.x * LPB;
    const int tid  = threadIdx.x;

    const float4* gx = (const float4*)(f + base);
    const float4* gy = (const float4*)(f + NPTS   + base);
    const float4* gz = (const float4*)(f + 2*NPTS + base);
    float4* sx4 = (float4*)xs; float4* sy4 = (float4*)ys; float4* sz4 = (float4*)zs;
    #pragma unroll
    for (int i = tid; i < LPB/4; i += 256) { sx4[i] = gx[i]; sy4[i] = gy[i]; sz4[i] = gz[i]; }
    __syncthreads();

    const int k    = tid & 63;
    const int slot = tid >> 6;
    const float wx = W[k]       * LOG2E;
    const float wy = W[64 + k]  * LOG2E;
    const float wz = W[128 + k] * LOG2E;
    const ull wx2 = pack2(wx, wx), wy2 = pack2(wy, wy), wz2 = pack2(wz, wz);

    ull S2 = 0, AX2 = 0, AY2 = 0, AZ2 = 0;   // {0.f,0.f} bit pattern

    const F4u* X = (const F4u*)xs + slot * (LPB/16);  // 128 float4 per slot
    const F4u* Y = (const F4u*)ys + slot * (LPB/16);
    const F4u* Z = (const F4u*)zs + slot * (LPB/16);

    #pragma unroll 4
    for (int i = 0; i < LPB/16; i++) {
        F4u px = X[i], py = Y[i], pz = Z[i];
        ull l01 = fma2(wx2, px.u[0], fma2(wy2, py.u[0], mul2(wz2, pz.u[0])));
        ull l23 = fma2(wx2, px.u[1], fma2(wy2, py.u[1], mul2(wz2, pz.u[1])));
        float f0, f1, f2, f3;
        unpack2(l01, f0, f1); unpack2(l23, f2, f3);
        ull e01 = pack2(ex2f(f0), ex2f(f1));
        ull e23 = pack2(ex2f(f2), ex2f(f3));
        S2  = add2(S2, e01);               S2  = add2(S2, e23);
        AX2 = fma2(e01, px.u[0], AX2);     AX2 = fma2(e23, px.u[1], AX2);
        AY2 = fma2(e01, py.u[0], AY2);     AY2 = fma2(e23, py.u[1], AY2);
        AZ2 = fma2(e01, pz.u[0], AZ2);     AZ2 = fma2(e23, pz.u[1], AZ2);
    }

    float s0, s1, x0, x1, y0, y1, z0, z1;
    unpack2(S2, s0, s1); unpack2(AX2, x0, x1); unpack2(AY2, y0, y1); unpack2(AZ2, z0, z1);
    float S = s0 + s1, AX = x0 + x1, AY = y0 + y1, AZ = z0 + z1;

    __syncthreads();                        // done reading point smem
    xs[tid] = S; xs[256 + tid] = AX; xs[512 + tid] = AY; xs[768 + tid] = AZ;
    __syncthreads();
    if (slot == 0) {
        float TS = 0.f, TX = 0.f, TY = 0.f, TZ = 0.f;
        #pragma unroll
        for (int o = 0; o < 4; o++) {
            int j = o * 64 + k;
            TS += xs[j]; TX += xs[256 + j]; TY += xs[512 + j]; TZ += xs[768 + j];
        }
        float* p = g_part[bt][blockIdx.x][k];
        p[0] = TS; p[1] = TX; p[2] = TY; p[3] = TZ;
    }
}

// ---------------------------------------------------------------------------
// Kernel BC (fused): reduce chunks -> mu, then per-batch 3x3 polar + R,T.
// One block per batch, 128 threads (t = tid>>6 selects template/source).
// ---------------------------------------------------------------------------
__device__ void polar3(const float* Win, float* Q)
{
    float X[9];
    #pragma unroll
    for (int i = 0; i < 9; i++) X[i] = Win[i];
    #pragma unroll 1
    for (int it = 0; it < 18; it++) {
        float c00 = X[4]*X[8] - X[5]*X[7];
        float c01 = X[5]*X[6] - X[3]*X[8];
        float c02 = X[3]*X[7] - X[4]*X[6];
        float c10 = X[2]*X[7] - X[1]*X[8];
        float c11 = X[0]*X[8] - X[2]*X[6];
        float c12 = X[1]*X[6] - X[0]*X[7];
        float c20 = X[1]*X[5] - X[2]*X[4];
        float c21 = X[2]*X[3] - X[0]*X[5];
        float c22 = X[0]*X[4] - X[1]*X[3];
        float det = X[0]*c00 + X[1]*c01 + X[2]*c02;
        float g  = ex2f(-0.3333333333f * lg2f(fabsf(det)));  // |det|^(-1/3)
        float h  = 0.5f * g;
        float h2 = __fdividef(0.5f, g * det);
        X[0] = h*X[0] + h2*c00; X[1] = h*X[1] + h2*c01; X[2] = h*X[2] + h2*c02;
        X[3] = h*X[3] + h2*c10; X[4] = h*X[4] + h2*c11; X[5] = h*X[5] + h2*c12;
        X[6] = h*X[6] + h2*c20; X[7] = h*X[7] + h2*c21; X[8] = h*X[8] + h2*c22;
    }
    #pragma unroll
    for (int i = 0; i < 9; i++) Q[i] = X[i];
}

__global__ void __launch_bounds__(128) kBC()
{
    __shared__ float mus[2][KK][3];   // [t][k][d], t=0 template, t=1 source
    const int b = blockIdx.x;
    const int tid = threadIdx.x;
    const int t  = tid >> 6;
    const int k  = tid & 63;
    const int bt = t * 8 + b;

    float S = 0.f, AX = 0.f, AY = 0.f, AZ = 0.f;
    #pragma unroll
    for (int c = 0; c < CH; c++) {
        float4 p = *(const float4*)g_part[bt][c][k];
        S += p.x; AX += p.y; AY += p.z; AZ += p.w;
    }
    float inv = INV_DENOM / S;
    mus[t][k][0] = AX * inv;
    mus[t][k][1] = AY * inv;
    mus[t][k][2] = AZ * inv;
    __syncthreads();

    if (tid < 32) {
        const int lane = tid;
        float ms0[3], ms1[3], mt0[3], mt1[3];
        #pragma unroll
        for (int d = 0; d < 3; d++) {
            ms0[d] = mus[1][lane][d];      ms1[d] = mus[1][lane + 32][d];
            mt0[d] = mus[0][lane][d];      mt1[d] = mus[0][lane + 32][d];
        }
        float ss[3], st[3];
        #pragma unroll
        for (int d = 0; d < 3; d++) { ss[d] = ms0[d] + ms1[d]; st[d] = mt0[d] + mt1[d]; }
        #pragma unroll
        for (int off = 16; off; off >>= 1)
            #pragma unroll
            for (int d = 0; d < 3; d++) {
                ss[d] += __shfl_xor_sync(0xffffffffu, ss[d], off);
                st[d] += __shfl_xor_sync(0xffffffffu, st[d], off);
            }
        float cx[3], cy[3];
        #pragma unroll
        for (int d = 0; d < 3; d++) { cx[d] = PI_CONST * ss[d]; cy[d] = PI_CONST * st[d]; }

        float Wm[9];
        #pragma unroll
        for (int d = 0; d < 3; d++)
            #pragma unroll
            for (int e = 0; e < 3; e++)
                Wm[d*3+e] = (mt0[d] - cy[d]) * (ms0[e] - cx[e])
                          + (mt1[d] - cy[d]) * (ms1[e] - cx[e]);
        #pragma unroll
        for (int off = 16; off; off >>= 1)
            #pragma unroll
            for (int i = 0; i < 9; i++)
                Wm[i] += __shfl_xor_sync(0xffffffffu, Wm[i], off);

        if (lane == 0) {
            #pragma unroll
            for (int i = 0; i < 9; i++) Wm[i] *= PI_CONST;
            float Q[9];
            polar3(Wm, Q);
            float det = Q[0]*(Q[4]*Q[8]-Q[5]*Q[7])
                      - Q[1]*(Q[3]*Q[8]-Q[5]*Q[6])
                      + Q[2]*(Q[3]*Q[7]-Q[4]*Q[6]);
            if (det < 0.f) { Q[2] = -Q[2]; Q[5] = -Q[5]; Q[8] = -Q[8]; }
            float T0 = cy[0] - (Q[0]*cx[0] + Q[1]*cx[1] + Q[2]*cx[2]);
            float T1 = cy[1] - (Q[3]*cx[0] + Q[4]*cx[1] + Q[5]*cx[2]);
            float T2 = cy[2] - (Q[6]*cx[0] + Q[7]*cx[1] + Q[8]*cx[2]);
            float* rt = g_RT[b];
            #pragma unroll
            for (int i = 0; i < 9; i++) rt[i] = Q[i];
            rt[9] = T0; rt[10] = T1; rt[11] = T2;
        }
    }
}

// ---------------------------------------------------------------------------
// Kernel D: aligned[b,n,:] = R * src_pts[b,n,:] + T.
// 1024 blocks x 128 threads (more blocks/SM than before); src is L2-hot.
// ---------------------------------------------------------------------------
__global__ void __launch_bounds__(128) kD(const float* __restrict__ src,
                                          float* __restrict__ out)
{
    __shared__ float4 so[384];
    __shared__ float rt[12];
    const int b = blockIdx.x >> 7;
    const int tile = blockIdx.x & 127;
    const int tid = threadIdx.x;

    const float* f = src + (size_t)b * 3 * NPTS + tile * 512;
    float4 px = *(const float4*)(f + tid * 4);
    float4 py = *(const float4*)(f + NPTS + tid * 4);
    float4 pz = *(const float4*)(f + 2*NPTS + tid * 4);

    if (tid < 12) rt[tid] = g_RT[b][tid];
    __syncthreads();

    float r0 = rt[0], r1 = rt[1], r2 = rt[2];
    float r3 = rt[3], r4 = rt[4], r5 = rt[5];
    float r6 = rt[6], r7 = rt[7], r8 = rt[8];
    float t0 = rt[9], t1 = rt[10], t2 = rt[11];

    float X[4] = {px.x, px.y, px.z, px.w};
    float Y[4] = {py.x, py.y, py.z, py.w};
    float Z[4] = {pz.x, pz.y, pz.z, pz.w};
    float o[12];
    #pragma unroll
    for (int j = 0; j < 4; j++) {
        o[j*3 + 0] = fmaf(r0, X[j], fmaf(r1, Y[j], fmaf(r2, Z[j], t0)));
        o[j*3 + 1] = fmaf(r3, X[j], fmaf(r4, Y[j], fmaf(r5, Z[j], t1)));
        o[j*3 + 2] = fmaf(r6, X[j], fmaf(r7, Y[j], fmaf(r8, Z[j], t2)));
    }
    #pragma unroll
    for (int j = 0; j < 3; j++)
        so[tid*3 + j] = make_float4(o[j*4+0], o[j*4+1], o[j*4+2], o[j*4+3]);
    __syncthreads();

    float4* ob = (float4*)(out + ((size_t)b * NPTS + tile * 512) * 3);
    #pragma unroll
    for (int i = tid; i < 384; i += 128) ob[i] = so[i];
}

// ---------------------------------------------------------------------------
extern "C" void kernel_launch(void* const* d_in, const int* in_sizes, int n_in,
                              void* d_out, int out_size)
{
    const float* tmpl = (const float*)d_in[0];   // (8,3,65536)
    const float* src  = (const float*)d_in[1];   // (8,3,65536)
    const float* W    = (const float*)d_in[2];   // (3,64)
    float* out        = (float*)d_out;           // (8,65536,3)

    kA<<<dim3(CH, 16), 256>>>(tmpl, src, W);
    kBC<<<BB, 128>>>();
    kD<<<BB * (NPTS / 512), 128>>>(src, out);
}

// round 3
// speedup vs baseline: 1.3631x; 1.0577x over previous
#include <cuda_runtime.h>
#include <math_constants.h>
#include <cstdint>

typedef unsigned long long ull;

#define NPTS 65536
#define KK   64
#define CH   64          // chunks over N for kernel A (doubled: occupancy)
#define LPB  (NPTS/CH)   // 1024 points per block in kernel A
#define BB   8
#define LOG2E 1.4426950408889634f
#define PI_CONST ((1.0f + 1e-8f) / 65536.0f)
#define INV_DENOM (1.0f / (1.0f + 2e-8f))

// Scratch (device globals: no allocation allowed)
__device__ float g_part[16][CH][KK][4];   // [bt][chunk][k][{S, Sx, Sy, Sz}]
__device__ float g_RT[BB][12];            // 9 R (row major) + 3 T

__device__ __forceinline__ float ex2f(float x) {
    float r; asm("ex2.approx.f32 %0, %1;" : "=f"(r) : "f"(x)); return r;
}
__device__ __forceinline__ float lg2f(float x) {
    float r; asm("lg2.approx.f32 %0, %1;" : "=f"(r) : "f"(x)); return r;
}

// ---- packed f32x2 helpers (Blackwell) ----
__device__ __forceinline__ ull fma2(ull a, ull b, ull c) {
    ull d; asm("fma.rn.f32x2 %0, %1, %2, %3;" : "=l"(d) : "l"(a), "l"(b), "l"(c)); return d;
}
__device__ __forceinline__ ull mul2(ull a, ull b) {
    ull d; asm("mul.rn.f32x2 %0, %1, %2;" : "=l"(d) : "l"(a), "l"(b)); return d;
}
__device__ __forceinline__ ull add2(ull a, ull b) {
    ull d; asm("add.rn.f32x2 %0, %1, %2;" : "=l"(d) : "l"(a), "l"(b)); return d;
}
__device__ __forceinline__ ull pack2(float lo, float hi) {
    ull r; asm("mov.b64 %0, {%1, %2};" : "=l"(r) : "f"(lo), "f"(hi)); return r;
}
__device__ __forceinline__ void unpack2(ull v, float& lo, float& hi) {
    asm("mov.b64 {%0, %1}, %2;" : "=f"(lo), "=f"(hi) : "l"(v));
}

union F4u { float4 f; ull u[2]; };

// ---------------------------------------------------------------------------
// Kernel A: per (b, tensor, chunk): plain-sum softmax numerators for all K=64.
// No max-tracking (logits bounded; fp32 range ample). Packed f32x2 math.
// Block = 256 threads = 64 k-lanes x 4 point-slots. Points staged in smem
// (warp-broadcast reads). 1024 blocks for occupancy/latency hiding.
// ---------------------------------------------------------------------------
__global__ void __launch_bounds__(256) kA(const float* __restrict__ tmpl,
                                          const float* __restrict__ src,
                                          const float* __restrict__ W)
{
    __shared__ float xs[LPB], ys[LPB], zs[LPB];
    const int bt = blockIdx.y;
    const int b  = bt & 7;
    const int t  = bt >> 3;
    const float* f = (t ? src : tmpl) + (size_t)b * 3 * NPTS;
    const int base = blockIdx.x * LPB;
    const int tid  = threadIdx.x;

    const float4* gx = (const float4*)(f + base);
    const float4* gy = (const float4*)(f + NPTS   + base);
    const float4* gz = (const float4*)(f + 2*NPTS + base);
    float4* sx4 = (float4*)xs; float4* sy4 = (float4*)ys; float4* sz4 = (float4*)zs;
    if (tid < LPB/4) { sx4[tid] = gx[tid]; sy4[tid] = gy[tid]; sz4[tid] = gz[tid]; }
    __syncthreads();

    const int k    = tid & 63;
    const int slot = tid >> 6;
    const float wx = W[k]       * LOG2E;
    const float wy = W[64 + k]  * LOG2E;
    const float wz = W[128 + k] * LOG2E;
    const ull wx2 = pack2(wx, wx), wy2 = pack2(wy, wy), wz2 = pack2(wz, wz);

    ull S2 = 0, AX2 = 0, AY2 = 0, AZ2 = 0;

    const F4u* X = (const F4u*)xs + slot * (LPB/16);  // 64 float4 per slot
    const F4u* Y = (const F4u*)ys + slot * (LPB/16);
    const F4u* Z = (const F4u*)zs + slot * (LPB/16);

    #pragma unroll 8
    for (int i = 0; i < LPB/16; i++) {
        F4u px = X[i], py = Y[i], pz = Z[i];
        ull l01 = fma2(wx2, px.u[0], fma2(wy2, py.u[0], mul2(wz2, pz.u[0])));
        ull l23 = fma2(wx2, px.u[1], fma2(wy2, py.u[1], mul2(wz2, pz.u[1])));
        float f0, f1, f2, f3;
        unpack2(l01, f0, f1); unpack2(l23, f2, f3);
        ull e01 = pack2(ex2f(f0), ex2f(f1));
        ull e23 = pack2(ex2f(f2), ex2f(f3));
        S2  = add2(S2, e01);               S2  = add2(S2, e23);
        AX2 = fma2(e01, px.u[0], AX2);     AX2 = fma2(e23, px.u[1], AX2);
        AY2 = fma2(e01, py.u[0], AY2);     AY2 = fma2(e23, py.u[1], AY2);
        AZ2 = fma2(e01, pz.u[0], AZ2);     AZ2 = fma2(e23, pz.u[1], AZ2);
    }

    float s0, s1, x0, x1, y0, y1, z0, z1;
    unpack2(S2, s0, s1); unpack2(AX2, x0, x1); unpack2(AY2, y0, y1); unpack2(AZ2, z0, z1);
    float S = s0 + s1, AX = x0 + x1, AY = y0 + y1, AZ = z0 + z1;

    __syncthreads();                        // done reading point smem
    xs[tid] = S; xs[256 + tid] = AX; xs[512 + tid] = AY; xs[768 + tid] = AZ;
    __syncthreads();
    if (slot == 0) {
        float TS = 0.f, TX = 0.f, TY = 0.f, TZ = 0.f;
        #pragma unroll
        for (int o = 0; o < 4; o++) {
            int j = o * 64 + k;
            TS += xs[j]; TX += xs[256 + j]; TY += xs[512 + j]; TZ += xs[768 + j];
        }
        float* p = g_part[bt][blockIdx.x][k];
        p[0] = TS; p[1] = TX; p[2] = TY; p[3] = TZ;
    }
}

// ---------------------------------------------------------------------------
// Kernel BC (fused): reduce chunks -> mu, then per-batch 3x3 polar + R,T.
// One block per batch, 128 threads (t = tid>>6 selects template/source).
// ---------------------------------------------------------------------------
__device__ void polar3(const float* Win, float* Q)
{
    float X[9];
    #pragma unroll
    for (int i = 0; i < 9; i++) X[i] = Win[i];
    #pragma unroll 1
    for (int it = 0; it < 18; it++) {
        float c00 = X[4]*X[8] - X[5]*X[7];
        float c01 = X[5]*X[6] - X[3]*X[8];
        float c02 = X[3]*X[7] - X[4]*X[6];
        float c10 = X[2]*X[7] - X[1]*X[8];
        float c11 = X[0]*X[8] - X[2]*X[6];
        float c12 = X[1]*X[6] - X[0]*X[7];
        float c20 = X[1]*X[5] - X[2]*X[4];
        float c21 = X[2]*X[3] - X[0]*X[5];
        float c22 = X[0]*X[4] - X[1]*X[3];
        float det = X[0]*c00 + X[1]*c01 + X[2]*c02;
        float g  = ex2f(-0.3333333333f * lg2f(fabsf(det)));  // |det|^(-1/3)
        float h  = 0.5f * g;
        float h2 = __fdividef(0.5f, g * det);
        X[0] = h*X[0] + h2*c00; X[1] = h*X[1] + h2*c01; X[2] = h*X[2] + h2*c02;
        X[3] = h*X[3] + h2*c10; X[4] = h*X[4] + h2*c11; X[5] = h*X[5] + h2*c12;
        X[6] = h*X[6] + h2*c20; X[7] = h*X[7] + h2*c21; X[8] = h*X[8] + h2*c22;
    }
    #pragma unroll
    for (int i = 0; i < 9; i++) Q[i] = X[i];
}

__global__ void __launch_bounds__(128) kBC()
{
    __shared__ float mus[2][KK][3];   // [t][k][d]
    const int b = blockIdx.x;
    const int tid = threadIdx.x;
    const int t  = tid >> 6;
    const int k  = tid & 63;
    const int bt = t * 8 + b;

    float S = 0.f, AX = 0.f, AY = 0.f, AZ = 0.f;
    #pragma unroll 8
    for (int c = 0; c < CH; c++) {
        float4 p = *(const float4*)g_part[bt][c][k];
        S += p.x; AX += p.y; AY += p.z; AZ += p.w;
    }
    float inv = INV_DENOM / S;
    mus[t][k][0] = AX * inv;
    mus[t][k][1] = AY * inv;
    mus[t][k][2] = AZ * inv;
    __syncthreads();

    if (tid < 32) {
        const int lane = tid;
        float ms0[3], ms1[3], mt0[3], mt1[3];
        #pragma unroll
        for (int d = 0; d < 3; d++) {
            ms0[d] = mus[1][lane][d];      ms1[d] = mus[1][lane + 32][d];
            mt0[d] = mus[0][lane][d];      mt1[d] = mus[0][lane + 32][d];
        }
        float ss[3], st[3];
        #pragma unroll
        for (int d = 0; d < 3; d++) { ss[d] = ms0[d] + ms1[d]; st[d] = mt0[d] + mt1[d]; }
        #pragma unroll
        for (int off = 16; off; off >>= 1)
            #pragma unroll
            for (int d = 0; d < 3; d++) {
                ss[d] += __shfl_xor_sync(0xffffffffu, ss[d], off);
                st[d] += __shfl_xor_sync(0xffffffffu, st[d], off);
            }
        float cx[3], cy[3];
        #pragma unroll
        for (int d = 0; d < 3; d++) { cx[d] = PI_CONST * ss[d]; cy[d] = PI_CONST * st[d]; }

        float Wm[9];
        #pragma unroll
        for (int d = 0; d < 3; d++)
            #pragma unroll
            for (int e = 0; e < 3; e++)
                Wm[d*3+e] = (mt0[d] - cy[d]) * (ms0[e] - cx[e])
                          + (mt1[d] - cy[d]) * (ms1[e] - cx[e]);
        #pragma unroll
        for (int off = 16; off; off >>= 1)
            #pragma unroll
            for (int i = 0; i < 9; i++)
                Wm[i] += __shfl_xor_sync(0xffffffffu, Wm[i], off);

        if (lane == 0) {
            #pragma unroll
            for (int i = 0; i < 9; i++) Wm[i] *= PI_CONST;
            float Q[9];
            polar3(Wm, Q);
            float det = Q[0]*(Q[4]*Q[8]-Q[5]*Q[7])
                      - Q[1]*(Q[3]*Q[8]-Q[5]*Q[6])
                      + Q[2]*(Q[3]*Q[7]-Q[4]*Q[6]);
            if (det < 0.f) { Q[2] = -Q[2]; Q[5] = -Q[5]; Q[8] = -Q[8]; }
            float T0 = cy[0] - (Q[0]*cx[0] + Q[1]*cx[1] + Q[2]*cx[2]);
            float T1 = cy[1] - (Q[3]*cx[0] + Q[4]*cx[1] + Q[5]*cx[2]);
            float T2 = cy[2] - (Q[6]*cx[0] + Q[7]*cx[1] + Q[8]*cx[2]);
            float* rt = g_RT[b];
            #pragma unroll
            for (int i = 0; i < 9; i++) rt[i] = Q[i];
            rt[9] = T0; rt[10] = T1; rt[11] = T2;
        }
    }
}

// ---------------------------------------------------------------------------
// Kernel D: aligned[b,n,:] = R * src_pts[b,n,:] + T.
// ---------------------------------------------------------------------------
__global__ void __launch_bounds__(128) kD(const float* __restrict__ src,
                                          float* __restrict__ out)
{
    __shared__ float4 so[384];
    __shared__ float rt[12];
    const int b = blockIdx.x >> 7;
    const int tile = blockIdx.x & 127;
    const int tid = threadIdx.x;

    const float* f = src + (size_t)b * 3 * NPTS + tile * 512;
    float4 px = *(const float4*)(f + tid * 4);
    float4 py = *(const float4*)(f + NPTS + tid * 4);
    float4 pz = *(const float4*)(f + 2*NPTS + tid * 4);

    if (tid < 12) rt[tid] = g_RT[b][tid];
    __syncthreads();

    float r0 = rt[0], r1 = rt[1], r2 = rt[2];
    float r3 = rt[3], r4 = rt[4], r5 = rt[5];
    float r6 = rt[6], r7 = rt[7], r8 = rt[8];
    float t0 = rt[9], t1 = rt[10], t2 = rt[11];

    float X[4] = {px.x, px.y, px.z, px.w};
    float Y[4] = {py.x, py.y, py.z, py.w};
    float Z[4] = {pz.x, pz.y, pz.z, pz.w};
    float o[12];
    #pragma unroll
    for (int j = 0; j < 4; j++) {
        o[j*3 + 0] = fmaf(r0, X[j], fmaf(r1, Y[j], fmaf(r2, Z[j], t0)));
        o[j*3 + 1] = fmaf(r3, X[j], fmaf(r4, Y[j], fmaf(r5, Z[j], t1)));
        o[j*3 + 2] = fmaf(r6, X[j], fmaf(r7, Y[j], fmaf(r8, Z[j], t2)));
    }
    #pragma unroll
    for (int j = 0; j < 3; j++)
        so[tid*3 + j] = make_float4(o[j*4+0], o[j*4+1], o[j*4+2], o[j*4+3]);
    __syncthreads();

    float4* ob = (float4*)(out + ((size_t)b * NPTS + tile * 512) * 3);
    #pragma unroll
    for (int i = tid; i < 384; i += 128) ob[i] = so[i];
}

// ---------------------------------------------------------------------------
extern "C" void kernel_launch(void* const* d_in, const int* in_sizes, int n_in,
                              void* d_out, int out_size)
{
    const float* tmpl = (const float*)d_in[0];   // (8,3,65536)
    const float* src  = (const float*)d_in[1];   // (8,3,65536)
    const float* W    = (const float*)d_in[2];   // (3,64)
    float* out        = (float*)d_out;           // (8,65536,3)

    kA<<<dim3(CH, 16), 256>>>(tmpl, src, W);
    kBC<<<BB, 128>>>();
    kD<<<BB * (NPTS / 512), 128>>>(src, out);
}